// round 14
// baseline (speedup 1.0000x reference)
#include <cuda_runtime.h>
#include <cuda_fp16.h>
#include <stdint.h>

// MessageFunction via mma.sync m16n8k16 fp16 (fp32 accum), persistent CTAs.
// R14: true 3 CTAs/SM. R13 failed residency because 77KB smem rounds to
//      80KB granules (3x80 > 228KB). Fix: drop the H tile from smem --
//      hreg lanes load coalesced LDG.64 directly from h_w (latency hidden
//      under GEMM1+GEMM2). 56KB/CTA x3 = 168KB resident. Padded E stride,
//      warp-private no-barrier cp.async pipeline, <=84-reg body.

#define TPB   256
#define TILE  256
#define ESTR  20

// ---- smem float offsets (per CTA 56576 bytes -> 56KB granule; x3 = 168KB) ----
#define OF_W2F 0       // 8192 fl: W2 B-frags uint2[ks(4)][ntg(32)][lane(32)]
#define OF_W1F 8192    // 512 fl : W1 B-frags uint2[nt(8)][lane(32)]
#define OF_B1  8704    // 64
#define OF_B2  8768    // 256
#define OF_E   9024    // 5120 fl : e tile f32 [256][stride 20]
#define SMEM_FLOATS 14144   // 56576 bytes

__device__ __forceinline__ uint32_t pack_h2(float a, float b) {
    __half2 h = __floats2half2_rn(a, b);
    return *(uint32_t*)&h;
}
__device__ __forceinline__ uint32_t smem_u32(const void* p) {
    uint32_t a;
    asm("{ .reg .u64 t; cvta.to.shared.u64 t, %1; cvt.u32.u64 %0, t; }" : "=r"(a) : "l"(p));
    return a;
}

// Not volatile: pure register computation; let ptxas pipeline it.
#define MMA_F16(d, a, b0, b1) \
    asm("mma.sync.aligned.m16n8k16.row.col.f32.f16.f16.f32 " \
        "{%0,%1,%2,%3}, {%4,%5,%6,%7}, {%8,%9}, {%0,%1,%2,%3};" \
        : "+f"((d)[0]), "+f"((d)[1]), "+f"((d)[2]), "+f"((d)[3]) \
        : "r"((a)[0]), "r"((a)[1]), "r"((a)[2]), "r"((a)[3]), \
          "r"(b0), "r"(b1))

__device__ __forceinline__ void red_add_v2(float* p, float a, float b) {
    asm volatile("red.global.add.v2.f32 [%0], {%1,%2};"
                 :: "l"(p), "f"(a), "f"(b) : "memory");
}
__device__ __forceinline__ void cp16(uint32_t s, const void* g) {
    asm volatile("cp.async.cg.shared.global [%0], [%1], 16;" :: "r"(s), "l"(g));
}
__device__ __forceinline__ void cp_commit() {
    asm volatile("cp.async.commit_group;" ::: "memory");
}
__device__ __forceinline__ void cp_wait_all() {
    asm volatile("cp.async.wait_group 0;" ::: "memory");
}

extern "C" __global__ void __launch_bounds__(TPB, 3)
msg_mma_kernel(const int* __restrict__ index_v,
               const float* __restrict__ h_w,
               const float* __restrict__ e_vw,
               const float* __restrict__ W1,
               const float* __restrict__ b1,
               const float* __restrict__ W2,
               const float* __restrict__ b2,
               float* __restrict__ out,
               int n_edge) {
    extern __shared__ float sm[];
    const uint32_t sb = smem_u32(sm);
    const int tid  = threadIdx.x;
    const int warp = tid >> 5;
    const int lane = tid & 31;
    const int q = lane & 3;       // quad col
    const int g = lane >> 2;      // group row

    // ================= stage weight fragments (once per CTA) =================
    for (int s = tid; s < 4096; s += TPB) {
        int ks = s >> 10, rest = s & 1023, ntg = rest >> 5, ln = rest & 31;
        int qq = ln & 3, gg = ln >> 2;
        int n = ntg * 8 + gg, r0 = ks * 16 + 2 * qq;
        uint2 b;
        b.x = pack_h2(W2[(r0)     * 256 + n], W2[(r0 + 1) * 256 + n]);
        b.y = pack_h2(W2[(r0 + 8) * 256 + n], W2[(r0 + 9) * 256 + n]);
        ((uint2*)(sm + OF_W2F))[s] = b;
    }
    for (int s = tid; s < 256; s += TPB) {
        int nt = s >> 5, ln = s & 31;
        int qq = ln & 3, gg = ln >> 2;
        int n = nt * 8 + gg;
        uint2 b;
        b.x = pack_h2(W1[(2 * qq)     * 64 + n], W1[(2 * qq + 1) * 64 + n]);
        b.y = pack_h2(W1[(2 * qq + 8) * 64 + n], W1[(2 * qq + 9) * 64 + n]);
        ((uint2*)(sm + OF_W1F))[s] = b;
    }
    if (tid < 64)  sm[OF_B1 + tid] = b1[tid];
    if (tid < 256) sm[OF_B2 + tid] = b2[tid];

    const int ntiles = (n_edge + TILE - 1) / TILE;

    // ---- async stage of E tile t: thread tid owns row tid (warp-private) ----
    auto stage = [&](int t) {
        const int base = t * TILE;
        const int rem  = n_edge - base;
        const int sr   = tid < rem ? tid : rem - 1;
        const char* ep = (const char*)(e_vw + (size_t)(base + sr) * 16);
        const uint32_t de = sb + (OF_E + tid * ESTR) * 4;
#pragma unroll
        for (int i = 0; i < 4; i++) cp16(de + 16 * i, ep + 16 * i);
        cp_commit();
    };

    __syncthreads();   // weights visible CTA-wide (E is warp-private)

    // ---- prologue ----
    if (blockIdx.x < ntiles) stage(blockIdx.x);

    for (int t = blockIdx.x; t < ntiles; t += gridDim.x) {
        const int base = t * TILE;

        // ---- hreg + nodes straight from global (coalesced LDG.64);
        //      issued first, consumed in epilogue -> latency hidden ----
        float hreg[2][2][4];
        int   node[2][2];
        bool  vld[2][2];
#pragma unroll
        for (int mt = 0; mt < 2; mt++)
#pragma unroll
            for (int rr = 0; rr < 2; rr++) {
                const int row = warp * 32 + mt * 16 + g + rr * 8;
                const int ge  = base + row;
                const bool v  = ge < n_edge;
                const int sr  = v ? ge : n_edge - 1;
                const float* Hr = h_w + (size_t)sr * 16;
                float2 h0 = __ldg((const float2*)(Hr + 2 * q));
                float2 h1 = __ldg((const float2*)(Hr + 8 + 2 * q));
                hreg[mt][rr][0] = h0.x; hreg[mt][rr][1] = h0.y;
                hreg[mt][rr][2] = h1.x; hreg[mt][rr][3] = h1.y;
                vld[mt][rr]  = v;
                node[mt][rr] = v ? __ldg(index_v + ge) : 0;
            }

        cp_wait_all();     // this warp's E rows landed
        __syncwarp();      // cross-lane smem visibility within the warp

        // ---- GEMM1 in two 16-row passes; build A-frags ha[2][4][4] ----
        uint32_t ha[2][4][4];
#pragma unroll
        for (int p = 0; p < 2; p++) {
            const int r0 = warp * 32 + p * 16 + g;
            const float* Er = sm + OF_E + r0 * ESTR;
            uint32_t ea[4];
            {
                float2 c0 = *(const float2*)(Er + 2 * q);
                float2 c1 = *(const float2*)(Er + 8 * ESTR + 2 * q);
                float2 c2 = *(const float2*)(Er + 8 + 2 * q);
                float2 c3 = *(const float2*)(Er + 8 * ESTR + 8 + 2 * q);
                ea[0] = pack_h2(c0.x, c0.y);
                ea[1] = pack_h2(c1.x, c1.y);
                ea[2] = pack_h2(c2.x, c2.y);
                ea[3] = pack_h2(c3.x, c3.y);
            }
            float acc1[8][4];
#pragma unroll
            for (int nt = 0; nt < 8; nt++)
#pragma unroll
                for (int r = 0; r < 4; r++) acc1[nt][r] = 0.0f;
#pragma unroll
            for (int nt = 0; nt < 8; nt++) {
                uint2 b = ((const uint2*)(sm + OF_W1F))[nt * 32 + lane];
                MMA_F16(acc1[nt], ea, b.x, b.y);
            }
#pragma unroll
            for (int nt = 0; nt < 8; nt++) {
                float2 bb = *(const float2*)(sm + OF_B1 + nt * 8 + 2 * q);
                float v0 = fmaxf(acc1[nt][0] + bb.x, 0.0f);
                float v1 = fmaxf(acc1[nt][1] + bb.y, 0.0f);
                float v2 = fmaxf(acc1[nt][2] + bb.x, 0.0f);
                float v3 = fmaxf(acc1[nt][3] + bb.y, 0.0f);
                int ks = nt >> 1, hi = (nt & 1) * 2;
                ha[p][ks][hi]     = pack_h2(v0, v1);   // row g
                ha[p][ks][hi + 1] = pack_h2(v2, v3);   // row g+8
            }
        }

        // ---- all E reads done for this warp: stage next tile now ----
        __syncwarp();
        const int tn = t + gridDim.x;
        if (tn < ntiles) stage(tn);

        // ---- GEMM2 + epilogue, 16 chunks of 16 cols (chunk c -> output m=c).
        //      Even chunks buffer their reduced value; odd chunks emit red_v2.
        float vbuf[2][2];
#pragma unroll
        for (int c = 0; c < 16; c++) {
            float acc[2][2][4];
#pragma unroll
            for (int mt = 0; mt < 2; mt++)
#pragma unroll
                for (int nt = 0; nt < 2; nt++)
#pragma unroll
                    for (int r = 0; r < 4; r++) acc[mt][nt][r] = 0.0f;
#pragma unroll
            for (int ks = 0; ks < 4; ks++)
#pragma unroll
                for (int nt = 0; nt < 2; nt++) {
                    uint2 b = ((const uint2*)(sm + OF_W2F))[(ks * 32 + c * 2 + nt) * 32 + lane];
                    MMA_F16(acc[0][nt], ha[0][ks], b.x, b.y);
                    MMA_F16(acc[1][nt], ha[1][ks], b.x, b.y);
                }
            float pacc[2][2];
            pacc[0][0] = 0.0f; pacc[0][1] = 0.0f;
            pacc[1][0] = 0.0f; pacc[1][1] = 0.0f;
#pragma unroll
            for (int nt = 0; nt < 2; nt++) {
                float2 bb = *(const float2*)(sm + OF_B2 + c * 16 + nt * 8 + 2 * q);
                const int hb = nt * 2;
#pragma unroll
                for (int mt = 0; mt < 2; mt++) {
                    pacc[mt][0] = fmaf(acc[mt][nt][0] + bb.x, hreg[mt][0][hb],     pacc[mt][0]);
                    pacc[mt][0] = fmaf(acc[mt][nt][1] + bb.y, hreg[mt][0][hb + 1], pacc[mt][0]);
                    pacc[mt][1] = fmaf(acc[mt][nt][2] + bb.x, hreg[mt][1][hb],     pacc[mt][1]);
                    pacc[mt][1] = fmaf(acc[mt][nt][3] + bb.y, hreg[mt][1][hb + 1], pacc[mt][1]);
                }
            }
#pragma unroll
            for (int mt = 0; mt < 2; mt++)
#pragma unroll
                for (int rr = 0; rr < 2; rr++) {
                    float v = pacc[mt][rr];
                    v += __shfl_xor_sync(0xFFFFFFFFu, v, 1);
                    v += __shfl_xor_sync(0xFFFFFFFFu, v, 2);
                    if ((c & 1) == 0) {
                        vbuf[mt][rr] = v;
                    } else if (q == 0 && vld[mt][rr]) {
                        red_add_v2(out + (size_t)node[mt][rr] * 16 + (c - 1),
                                   vbuf[mt][rr], v);
                    }
                }
        }
        // no __syncthreads: E rows are warp-private; pipeline is per-warp
    }
}

// ---------------- launch ----------------
extern "C" void kernel_launch(void* const* d_in, const int* in_sizes, int n_in,
                              void* d_out, int out_size) {
    const int*   index_v = nullptr;
    const float* h_w = nullptr;
    const float* e_vw = nullptr;
    const float* W1 = nullptr;
    const float* b1 = nullptr;
    const float* W2 = nullptr;
    const float* b2 = nullptr;

    int big_idx[8]; long long big_sz[8]; int nb = 0;
    for (int i = 0; i < n_in; i++) {
        long long s = in_sizes[i];
        if (s == 1024)       W1 = (const float*)d_in[i];
        else if (s == 64)    b1 = (const float*)d_in[i];
        else if (s == 16384) W2 = (const float*)d_in[i];
        else if (s == 256)   b2 = (const float*)d_in[i];
        else if (s > 100000 && nb < 8) { big_idx[nb] = i; big_sz[nb] = s; nb++; }
    }
    long long min_sz = big_sz[0]; int min_pos = 0;
    for (int i = 1; i < nb; i++)
        if (big_sz[i] < min_sz) { min_sz = big_sz[i]; min_pos = i; }
    index_v = (const int*)d_in[big_idx[min_pos]];
    int n_edge = (int)min_sz;
    bool got_h = false;
    for (int i = 0; i < nb; i++) {
        if (i == min_pos) continue;
        if (!got_h) { h_w = (const float*)d_in[big_idx[i]]; got_h = true; }
        else        { e_vw = (const float*)d_in[big_idx[i]]; }
    }

    float* out = (float*)d_out;
    cudaMemsetAsync(out, 0, (size_t)out_size * sizeof(float));

    static bool attr_set = false;
    if (!attr_set) {
        cudaFuncSetAttribute(msg_mma_kernel,
                             cudaFuncAttributeMaxDynamicSharedMemorySize,
                             SMEM_FLOATS * (int)sizeof(float));
        attr_set = true;
    }
    int ntiles = (n_edge + TILE - 1) / TILE;
    int grid = ntiles < 456 ? ntiles : 456;   // 3 CTAs/SM x 152 SMs
    msg_mma_kernel<<<grid, TPB, SMEM_FLOATS * sizeof(float)>>>(
        index_v, h_w, e_vw, W1, b1, W2, b2, out, n_edge);
}

// round 15
// speedup vs baseline: 1.3583x; 1.3583x over previous
#include <cuda_runtime.h>
#include <cuda_fp16.h>
#include <stdint.h>

// MessageFunction via mma.sync m16n8k16 fp16 (fp32 accum), persistent CTAs.
// R15: R11 base (2 CTAs/SM, 32 rows/warp, warp-private no-barrier cp.async
//      pipeline, padded E/H strides) + two L1TEX cuts:
//      (1) W2 B-fragments stored PAIRED -> one LDS.128 feeds 2 frags
//          (128 -> 64 LDS instrs per warp-tile);
//      (2) red.global.add.v4 scatter (halves RED lane-ops).

#define TPB   256
#define TILE  256
#define ESTR  20
#define HSTR  20

// ---- smem float offsets (per CTA 77056 bytes) ----
#define OF_W2F 0       // 8192 fl: W2 B-frag PAIRS uint4[ks(4)][pair(16)][lane(32)]
#define OF_W1F 8192    // 512 fl : W1 B-frags uint2[nt(8)][lane(32)]
#define OF_B1  8704    // 64
#define OF_B2  8768    // 256
#define OF_E   9024    // 5120 fl : e tile f32 [256][stride 20]
#define OF_H   14144   // 5120 fl : h tile f32 [256][stride 20]
#define SMEM_FLOATS 19264   // 77056 bytes

__device__ __forceinline__ uint32_t pack_h2(float a, float b) {
    __half2 h = __floats2half2_rn(a, b);
    return *(uint32_t*)&h;
}
__device__ __forceinline__ uint32_t smem_u32(const void* p) {
    uint32_t a;
    asm("{ .reg .u64 t; cvta.to.shared.u64 t, %1; cvt.u32.u64 %0, t; }" : "=r"(a) : "l"(p));
    return a;
}

// Not volatile: pure register computation; let ptxas pipeline it.
#define MMA_F16(d, a, b0, b1) \
    asm("mma.sync.aligned.m16n8k16.row.col.f32.f16.f16.f32 " \
        "{%0,%1,%2,%3}, {%4,%5,%6,%7}, {%8,%9}, {%0,%1,%2,%3};" \
        : "+f"((d)[0]), "+f"((d)[1]), "+f"((d)[2]), "+f"((d)[3]) \
        : "r"((a)[0]), "r"((a)[1]), "r"((a)[2]), "r"((a)[3]), \
          "r"(b0), "r"(b1))

__device__ __forceinline__ void red_add_v4(float* p, float a, float b,
                                           float c, float d) {
    asm volatile("red.global.add.v4.f32 [%0], {%1,%2,%3,%4};"
                 :: "l"(p), "f"(a), "f"(b), "f"(c), "f"(d) : "memory");
}
__device__ __forceinline__ void cp16(uint32_t s, const void* g) {
    asm volatile("cp.async.cg.shared.global [%0], [%1], 16;" :: "r"(s), "l"(g));
}
__device__ __forceinline__ void cp_commit() {
    asm volatile("cp.async.commit_group;" ::: "memory");
}
__device__ __forceinline__ void cp_wait_all() {
    asm volatile("cp.async.wait_group 0;" ::: "memory");
}

extern "C" __global__ void __launch_bounds__(TPB, 2)
msg_mma_kernel(const int* __restrict__ index_v,
               const float* __restrict__ h_w,
               const float* __restrict__ e_vw,
               const float* __restrict__ W1,
               const float* __restrict__ b1,
               const float* __restrict__ W2,
               const float* __restrict__ b2,
               float* __restrict__ out,
               int n_edge) {
    extern __shared__ float sm[];
    const uint32_t sb = smem_u32(sm);
    const int tid  = threadIdx.x;
    const int warp = tid >> 5;
    const int lane = tid & 31;
    const int q = lane & 3;       // quad col
    const int g = lane >> 2;      // group row

    // ================= stage weight fragments (once per CTA) =================
    // W2 B-frag pairs: uint4 { frag(2p).x, frag(2p).y, frag(2p+1).x, frag(2p+1).y }
    for (int s = tid; s < 2048; s += TPB) {
        int ks = s >> 9, p = (s >> 5) & 15, ln = s & 31;
        int qq = ln & 3, gg = ln >> 2;
        int r0 = ks * 16 + 2 * qq;
        uint4 u;
        {
            int n = (2 * p) * 8 + gg;
            u.x = pack_h2(W2[(r0)     * 256 + n], W2[(r0 + 1) * 256 + n]);
            u.y = pack_h2(W2[(r0 + 8) * 256 + n], W2[(r0 + 9) * 256 + n]);
        }
        {
            int n = (2 * p + 1) * 8 + gg;
            u.z = pack_h2(W2[(r0)     * 256 + n], W2[(r0 + 1) * 256 + n]);
            u.w = pack_h2(W2[(r0 + 8) * 256 + n], W2[(r0 + 9) * 256 + n]);
        }
        ((uint4*)(sm + OF_W2F))[s] = u;
    }
    for (int s = tid; s < 256; s += TPB) {
        int nt = s >> 5, ln = s & 31;
        int qq = ln & 3, gg = ln >> 2;
        int n = nt * 8 + gg;
        uint2 b;
        b.x = pack_h2(W1[(2 * qq)     * 64 + n], W1[(2 * qq + 1) * 64 + n]);
        b.y = pack_h2(W1[(2 * qq + 8) * 64 + n], W1[(2 * qq + 9) * 64 + n]);
        ((uint2*)(sm + OF_W1F))[s] = b;
    }
    if (tid < 64)  sm[OF_B1 + tid] = b1[tid];
    if (tid < 256) sm[OF_B2 + tid] = b2[tid];

    const int ntiles = (n_edge + TILE - 1) / TILE;

    // ---- async stage of tile t: thread tid owns row tid (warp-private) ----
    auto stage = [&](int t) {
        const int base = t * TILE;
        const int rem  = n_edge - base;
        const int sr   = tid < rem ? tid : rem - 1;
        const char* ep = (const char*)(e_vw + (size_t)(base + sr) * 16);
        const char* hp = (const char*)(h_w  + (size_t)(base + sr) * 16);
        const uint32_t de = sb + (OF_E + tid * ESTR) * 4;
        const uint32_t dh = sb + (OF_H + tid * HSTR) * 4;
#pragma unroll
        for (int i = 0; i < 4; i++) {
            cp16(de + 16 * i, ep + 16 * i);
            cp16(dh + 16 * i, hp + 16 * i);
        }
        cp_commit();
    };

    __syncthreads();   // weights visible CTA-wide (E/H are warp-private)

    // ---- prologue ----
    if (blockIdx.x < ntiles) stage(blockIdx.x);

    for (int t = blockIdx.x; t < ntiles; t += gridDim.x) {
        const int base = t * TILE;

        cp_wait_all();     // this warp's rows landed
        __syncwarp();      // cross-lane smem visibility within the warp

        // ---- GEMM1 in two 16-row passes; build A-frags ha[2][4][4] ----
        uint32_t ha[2][4][4];
#pragma unroll
        for (int p = 0; p < 2; p++) {
            const int r0 = warp * 32 + p * 16 + g;
            const float* Er = sm + OF_E + r0 * ESTR;
            uint32_t ea[4];
            {
                float2 c0 = *(const float2*)(Er + 2 * q);
                float2 c1 = *(const float2*)(Er + 8 * ESTR + 2 * q);
                float2 c2 = *(const float2*)(Er + 8 + 2 * q);
                float2 c3 = *(const float2*)(Er + 8 * ESTR + 8 + 2 * q);
                ea[0] = pack_h2(c0.x, c0.y);
                ea[1] = pack_h2(c1.x, c1.y);
                ea[2] = pack_h2(c2.x, c2.y);
                ea[3] = pack_h2(c3.x, c3.y);
            }
            float acc1[8][4];
#pragma unroll
            for (int nt = 0; nt < 8; nt++)
#pragma unroll
                for (int r = 0; r < 4; r++) acc1[nt][r] = 0.0f;
#pragma unroll
            for (int nt = 0; nt < 8; nt++) {
                uint2 b = ((const uint2*)(sm + OF_W1F))[nt * 32 + lane];
                MMA_F16(acc1[nt], ea, b.x, b.y);
            }
#pragma unroll
            for (int nt = 0; nt < 8; nt++) {
                float2 bb = *(const float2*)(sm + OF_B1 + nt * 8 + 2 * q);
                float v0 = fmaxf(acc1[nt][0] + bb.x, 0.0f);
                float v1 = fmaxf(acc1[nt][1] + bb.y, 0.0f);
                float v2 = fmaxf(acc1[nt][2] + bb.x, 0.0f);
                float v3 = fmaxf(acc1[nt][3] + bb.y, 0.0f);
                int ks = nt >> 1, hi = (nt & 1) * 2;
                ha[p][ks][hi]     = pack_h2(v0, v1);   // row g
                ha[p][ks][hi + 1] = pack_h2(v2, v3);   // row g+8
            }
        }

        // ---- h regs + nodes (warp-private rows) ----
        float hreg[2][2][4];
        int   node[2][2];
        bool  vld[2][2];
#pragma unroll
        for (int mt = 0; mt < 2; mt++)
#pragma unroll
            for (int rr = 0; rr < 2; rr++) {
                const int row = warp * 32 + mt * 16 + g + rr * 8;
                const float* Hr = sm + OF_H + row * HSTR;
                float2 h0 = *(const float2*)(Hr + 2 * q);
                float2 h1 = *(const float2*)(Hr + 8 + 2 * q);
                hreg[mt][rr][0] = h0.x; hreg[mt][rr][1] = h0.y;
                hreg[mt][rr][2] = h1.x; hreg[mt][rr][3] = h1.y;
                const int ge = base + row;
                vld[mt][rr]  = ge < n_edge;
                node[mt][rr] = vld[mt][rr] ? __ldg(index_v + ge) : 0;
            }

        // ---- all E/H reads done for this warp: stage next tile now ----
        __syncwarp();
        const int tn = t + gridDim.x;
        if (tn < ntiles) stage(tn);

        // ---- GEMM2 + epilogue, 8 chunks of 32 cols (m = 2c, 2c+1).
        //      Even chunk buffers its reduced m-pair; odd chunk emits red.v4.
        float vbuf[2][2][2];
#pragma unroll
        for (int c = 0; c < 8; c++) {
            float acc[2][4][4];
#pragma unroll
            for (int mt = 0; mt < 2; mt++)
#pragma unroll
                for (int nt = 0; nt < 4; nt++)
#pragma unroll
                    for (int r = 0; r < 4; r++) acc[mt][nt][r] = 0.0f;
#pragma unroll
            for (int ks = 0; ks < 4; ks++)
#pragma unroll
                for (int pp = 0; pp < 2; pp++) {
                    // pair pp covers ntg = c*4 + 2pp, c*4 + 2pp + 1
                    uint4 u = ((const uint4*)(sm + OF_W2F))[(ks * 16 + c * 2 + pp) * 32 + lane];
                    MMA_F16(acc[0][2 * pp],     ha[0][ks], u.x, u.y);
                    MMA_F16(acc[1][2 * pp],     ha[1][ks], u.x, u.y);
                    MMA_F16(acc[0][2 * pp + 1], ha[0][ks], u.z, u.w);
                    MMA_F16(acc[1][2 * pp + 1], ha[1][ks], u.z, u.w);
                }
            float pacc[2][2][2];
#pragma unroll
            for (int mt = 0; mt < 2; mt++)
#pragma unroll
                for (int rr = 0; rr < 2; rr++) {
                    pacc[mt][rr][0] = 0.0f; pacc[mt][rr][1] = 0.0f;
                }
#pragma unroll
            for (int nt = 0; nt < 4; nt++) {
                const int ntg = c * 4 + nt;
                float2 bb = *(const float2*)(sm + OF_B2 + ntg * 8 + 2 * q);
                const int hb = (nt & 1) * 2;
                const int ml = nt >> 1;
#pragma unroll
                for (int mt = 0; mt < 2; mt++) {
                    pacc[mt][0][ml] = fmaf(acc[mt][nt][0] + bb.x, hreg[mt][0][hb],     pacc[mt][0][ml]);
                    pacc[mt][0][ml] = fmaf(acc[mt][nt][1] + bb.y, hreg[mt][0][hb + 1], pacc[mt][0][ml]);
                    pacc[mt][1][ml] = fmaf(acc[mt][nt][2] + bb.x, hreg[mt][1][hb],     pacc[mt][1][ml]);
                    pacc[mt][1][ml] = fmaf(acc[mt][nt][3] + bb.y, hreg[mt][1][hb + 1], pacc[mt][1][ml]);
                }
            }
#pragma unroll
            for (int mt = 0; mt < 2; mt++)
#pragma unroll
                for (int rr = 0; rr < 2; rr++) {
#pragma unroll
                    for (int ml = 0; ml < 2; ml++) {
                        float v = pacc[mt][rr][ml];
                        v += __shfl_xor_sync(0xFFFFFFFFu, v, 1);
                        v += __shfl_xor_sync(0xFFFFFFFFu, v, 2);
                        pacc[mt][rr][ml] = v;
                    }
                    if ((c & 1) == 0) {
                        vbuf[mt][rr][0] = pacc[mt][rr][0];
                        vbuf[mt][rr][1] = pacc[mt][rr][1];
                    } else if (q == 0 && vld[mt][rr]) {
                        red_add_v4(out + (size_t)node[mt][rr] * 16 + 2 * (c - 1),
                                   vbuf[mt][rr][0], vbuf[mt][rr][1],
                                   pacc[mt][rr][0], pacc[mt][rr][1]);
                    }
                }
        }
        // no __syncthreads: E/H rows are warp-private; pipeline is per-warp
    }
}

// ---------------- launch ----------------
extern "C" void kernel_launch(void* const* d_in, const int* in_sizes, int n_in,
                              void* d_out, int out_size) {
    const int*   index_v = nullptr;
    const float* h_w = nullptr;
    const float* e_vw = nullptr;
    const float* W1 = nullptr;
    const float* b1 = nullptr;
    const float* W2 = nullptr;
    const float* b2 = nullptr;

    int big_idx[8]; long long big_sz[8]; int nb = 0;
    for (int i = 0; i < n_in; i++) {
        long long s = in_sizes[i];
        if (s == 1024)       W1 = (const float*)d_in[i];
        else if (s == 64)    b1 = (const float*)d_in[i];
        else if (s == 16384) W2 = (const float*)d_in[i];
        else if (s == 256)   b2 = (const float*)d_in[i];
        else if (s > 100000 && nb < 8) { big_idx[nb] = i; big_sz[nb] = s; nb++; }
    }
    long long min_sz = big_sz[0]; int min_pos = 0;
    for (int i = 1; i < nb; i++)
        if (big_sz[i] < min_sz) { min_sz = big_sz[i]; min_pos = i; }
    index_v = (const int*)d_in[big_idx[min_pos]];
    int n_edge = (int)min_sz;
    bool got_h = false;
    for (int i = 0; i < nb; i++) {
        if (i == min_pos) continue;
        if (!got_h) { h_w = (const float*)d_in[big_idx[i]]; got_h = true; }
        else        { e_vw = (const float*)d_in[big_idx[i]]; }
    }

    float* out = (float*)d_out;
    cudaMemsetAsync(out, 0, (size_t)out_size * sizeof(float));

    static bool attr_set = false;
    if (!attr_set) {
        cudaFuncSetAttribute(msg_mma_kernel,
                             cudaFuncAttributeMaxDynamicSharedMemorySize,
                             SMEM_FLOATS * (int)sizeof(float));
        attr_set = true;
    }
    int ntiles = (n_edge + TILE - 1) / TILE;
    int grid = ntiles < 304 ? ntiles : 304;   // 2 CTAs/SM x 152 SMs
    msg_mma_kernel<<<grid, TPB, SMEM_FLOATS * sizeof(float)>>>(
        index_v, h_w, e_vw, W1, b1, W2, b2, out, n_edge);
}

// round 16
// speedup vs baseline: 1.4178x; 1.0437x over previous
#include <cuda_runtime.h>
#include <cuda_fp16.h>
#include <stdint.h>

// MessageFunction via mma.sync m16n8k16 fp16 (fp32 accum), persistent CTAs.
// R16: R15 base + issue-stream cuts:
//      (1) packed fma.rn.f32x2 epilogue ((acc+bb)*h in 2-wide ops; bb and h
//          read as 64-bit packed operands straight from smem);
//      (2) W1 B-fragments paired -> LDS.128 (8 -> 4 loads in GEMM1).

#define TPB   256
#define TILE  256
#define ESTR  20
#define HSTR  20

// ---- smem float offsets (per CTA 77056 bytes) ----
#define OF_W2F 0       // 8192 fl: W2 B-frag PAIRS uint4[ks(4)][pair(16)][lane(32)]
#define OF_W1F 8192    // 512 fl : W1 B-frag PAIRS uint4[pair(4)][lane(32)]
#define OF_B1  8704    // 64
#define OF_B2  8768    // 256
#define OF_E   9024    // 5120 fl : e tile f32 [256][stride 20]
#define OF_H   14144   // 5120 fl : h tile f32 [256][stride 20]
#define SMEM_FLOATS 19264   // 77056 bytes

typedef unsigned long long u64;

__device__ __forceinline__ uint32_t pack_h2(float a, float b) {
    __half2 h = __floats2half2_rn(a, b);
    return *(uint32_t*)&h;
}
__device__ __forceinline__ uint32_t smem_u32(const void* p) {
    uint32_t a;
    asm("{ .reg .u64 t; cvta.to.shared.u64 t, %1; cvt.u32.u64 %0, t; }" : "=r"(a) : "l"(p));
    return a;
}
// ---- packed f32x2 helpers ----
__device__ __forceinline__ u64 pk2(float a, float b) {
    u64 d;
    asm("mov.b64 %0, {%1, %2};" : "=l"(d) : "f"(a), "f"(b));
    return d;
}
__device__ __forceinline__ u64 fadd2(u64 a, u64 b) {
    u64 d;
    asm("add.rn.f32x2 %0, %1, %2;" : "=l"(d) : "l"(a), "l"(b));
    return d;
}
__device__ __forceinline__ u64 ffma2(u64 a, u64 b, u64 c) {
    u64 d;
    asm("fma.rn.f32x2 %0, %1, %2, %3;" : "=l"(d) : "l"(a), "l"(b), "l"(c));
    return d;
}
__device__ __forceinline__ float losum(u64 v) {
    float lo, hi;
    asm("mov.b64 {%0, %1}, %2;" : "=f"(lo), "=f"(hi) : "l"(v));
    return lo + hi;
}

// Not volatile: pure register computation; let ptxas pipeline it.
#define MMA_F16(d, a, b0, b1) \
    asm("mma.sync.aligned.m16n8k16.row.col.f32.f16.f16.f32 " \
        "{%0,%1,%2,%3}, {%4,%5,%6,%7}, {%8,%9}, {%0,%1,%2,%3};" \
        : "+f"((d)[0]), "+f"((d)[1]), "+f"((d)[2]), "+f"((d)[3]) \
        : "r"((a)[0]), "r"((a)[1]), "r"((a)[2]), "r"((a)[3]), \
          "r"(b0), "r"(b1))

__device__ __forceinline__ void red_add_v4(float* p, float a, float b,
                                           float c, float d) {
    asm volatile("red.global.add.v4.f32 [%0], {%1,%2,%3,%4};"
                 :: "l"(p), "f"(a), "f"(b), "f"(c), "f"(d) : "memory");
}
__device__ __forceinline__ void cp16(uint32_t s, const void* g) {
    asm volatile("cp.async.cg.shared.global [%0], [%1], 16;" :: "r"(s), "l"(g));
}
__device__ __forceinline__ void cp_commit() {
    asm volatile("cp.async.commit_group;" ::: "memory");
}
__device__ __forceinline__ void cp_wait_all() {
    asm volatile("cp.async.wait_group 0;" ::: "memory");
}

extern "C" __global__ void __launch_bounds__(TPB, 2)
msg_mma_kernel(const int* __restrict__ index_v,
               const float* __restrict__ h_w,
               const float* __restrict__ e_vw,
               const float* __restrict__ W1,
               const float* __restrict__ b1,
               const float* __restrict__ W2,
               const float* __restrict__ b2,
               float* __restrict__ out,
               int n_edge) {
    extern __shared__ float sm[];
    const uint32_t sb = smem_u32(sm);
    const int tid  = threadIdx.x;
    const int warp = tid >> 5;
    const int lane = tid & 31;
    const int q = lane & 3;       // quad col
    const int g = lane >> 2;      // group row

    // ================= stage weight fragments (once per CTA) =================
    // W2 B-frag pairs: uint4 { frag(2p).x, frag(2p).y, frag(2p+1).x, frag(2p+1).y }
    for (int s = tid; s < 2048; s += TPB) {
        int ks = s >> 9, p = (s >> 5) & 15, ln = s & 31;
        int qq = ln & 3, gg = ln >> 2;
        int r0 = ks * 16 + 2 * qq;
        uint4 u;
        {
            int n = (2 * p) * 8 + gg;
            u.x = pack_h2(W2[(r0)     * 256 + n], W2[(r0 + 1) * 256 + n]);
            u.y = pack_h2(W2[(r0 + 8) * 256 + n], W2[(r0 + 9) * 256 + n]);
        }
        {
            int n = (2 * p + 1) * 8 + gg;
            u.z = pack_h2(W2[(r0)     * 256 + n], W2[(r0 + 1) * 256 + n]);
            u.w = pack_h2(W2[(r0 + 8) * 256 + n], W2[(r0 + 9) * 256 + n]);
        }
        ((uint4*)(sm + OF_W2F))[s] = u;
    }
    // W1 B-frag pairs
    for (int s = tid; s < 128; s += TPB) {
        int p = s >> 5, ln = s & 31;
        int qq = ln & 3, gg = ln >> 2;
        uint4 u;
        {
            int n = (2 * p) * 8 + gg;
            u.x = pack_h2(W1[(2 * qq)     * 64 + n], W1[(2 * qq + 1) * 64 + n]);
            u.y = pack_h2(W1[(2 * qq + 8) * 64 + n], W1[(2 * qq + 9) * 64 + n]);
        }
        {
            int n = (2 * p + 1) * 8 + gg;
            u.z = pack_h2(W1[(2 * qq)     * 64 + n], W1[(2 * qq + 1) * 64 + n]);
            u.w = pack_h2(W1[(2 * qq + 8) * 64 + n], W1[(2 * qq + 9) * 64 + n]);
        }
        ((uint4*)(sm + OF_W1F))[s] = u;
    }
    if (tid < 64)  sm[OF_B1 + tid] = b1[tid];
    if (tid < 256) sm[OF_B2 + tid] = b2[tid];

    const int ntiles = (n_edge + TILE - 1) / TILE;

    // ---- async stage of tile t: thread tid owns row tid (warp-private) ----
    auto stage = [&](int t) {
        const int base = t * TILE;
        const int rem  = n_edge - base;
        const int sr   = tid < rem ? tid : rem - 1;
        const char* ep = (const char*)(e_vw + (size_t)(base + sr) * 16);
        const char* hp = (const char*)(h_w  + (size_t)(base + sr) * 16);
        const uint32_t de = sb + (OF_E + tid * ESTR) * 4;
        const uint32_t dh = sb + (OF_H + tid * HSTR) * 4;
#pragma unroll
        for (int i = 0; i < 4; i++) {
            cp16(de + 16 * i, ep + 16 * i);
            cp16(dh + 16 * i, hp + 16 * i);
        }
        cp_commit();
    };

    __syncthreads();   // weights visible CTA-wide (E/H are warp-private)

    // ---- prologue ----
    if (blockIdx.x < ntiles) stage(blockIdx.x);

    for (int t = blockIdx.x; t < ntiles; t += gridDim.x) {
        const int base = t * TILE;

        cp_wait_all();     // this warp's rows landed
        __syncwarp();      // cross-lane smem visibility within the warp

        // ---- GEMM1 in two 16-row passes; build A-frags ha[2][4][4] ----
        uint32_t ha[2][4][4];
#pragma unroll
        for (int p = 0; p < 2; p++) {
            const int r0 = warp * 32 + p * 16 + g;
            const float* Er = sm + OF_E + r0 * ESTR;
            uint32_t ea[4];
            {
                float2 c0 = *(const float2*)(Er + 2 * q);
                float2 c1 = *(const float2*)(Er + 8 * ESTR + 2 * q);
                float2 c2 = *(const float2*)(Er + 8 + 2 * q);
                float2 c3 = *(const float2*)(Er + 8 * ESTR + 8 + 2 * q);
                ea[0] = pack_h2(c0.x, c0.y);
                ea[1] = pack_h2(c1.x, c1.y);
                ea[2] = pack_h2(c2.x, c2.y);
                ea[3] = pack_h2(c3.x, c3.y);
            }
            float acc1[8][4];
#pragma unroll
            for (int nt = 0; nt < 8; nt++)
#pragma unroll
                for (int r = 0; r < 4; r++) acc1[nt][r] = 0.0f;
#pragma unroll
            for (int p2 = 0; p2 < 4; p2++) {
                uint4 u = ((const uint4*)(sm + OF_W1F))[p2 * 32 + lane];
                MMA_F16(acc1[2 * p2],     ea, u.x, u.y);
                MMA_F16(acc1[2 * p2 + 1], ea, u.z, u.w);
            }
#pragma unroll
            for (int nt = 0; nt < 8; nt++) {
                float2 bb = *(const float2*)(sm + OF_B1 + nt * 8 + 2 * q);
                float v0 = fmaxf(acc1[nt][0] + bb.x, 0.0f);
                float v1 = fmaxf(acc1[nt][1] + bb.y, 0.0f);
                float v2 = fmaxf(acc1[nt][2] + bb.x, 0.0f);
                float v3 = fmaxf(acc1[nt][3] + bb.y, 0.0f);
                int ks = nt >> 1, hi = (nt & 1) * 2;
                ha[p][ks][hi]     = pack_h2(v0, v1);   // row g
                ha[p][ks][hi + 1] = pack_h2(v2, v3);   // row g+8
            }
        }

        // ---- h (packed u64 pairs) + nodes (warp-private rows) ----
        u64  hu[2][2][2];
        int  node[2][2];
        bool vld[2][2];
#pragma unroll
        for (int mt = 0; mt < 2; mt++)
#pragma unroll
            for (int rr = 0; rr < 2; rr++) {
                const int row = warp * 32 + mt * 16 + g + rr * 8;
                const float* Hr = sm + OF_H + row * HSTR;
                hu[mt][rr][0] = *(const u64*)(Hr + 2 * q);       // h[2q], h[2q+1]
                hu[mt][rr][1] = *(const u64*)(Hr + 8 + 2 * q);   // h[8+2q], h[8+2q+1]
                const int ge = base + row;
                vld[mt][rr]  = ge < n_edge;
                node[mt][rr] = vld[mt][rr] ? __ldg(index_v + ge) : 0;
            }

        // ---- all E/H reads done for this warp: stage next tile now ----
        __syncwarp();
        const int tn = t + gridDim.x;
        if (tn < ntiles) stage(tn);

        // ---- GEMM2 + epilogue, 8 chunks of 32 cols (m = 2c, 2c+1).
        //      Even chunk buffers its reduced m-pair; odd chunk emits red.v4.
        float vbuf[2][2][2];
#pragma unroll
        for (int c = 0; c < 8; c++) {
            float acc[2][4][4];
#pragma unroll
            for (int mt = 0; mt < 2; mt++)
#pragma unroll
                for (int nt = 0; nt < 4; nt++)
#pragma unroll
                    for (int r = 0; r < 4; r++) acc[mt][nt][r] = 0.0f;
#pragma unroll
            for (int ks = 0; ks < 4; ks++)
#pragma unroll
                for (int pp = 0; pp < 2; pp++) {
                    // pair pp covers ntg = c*4 + 2pp, c*4 + 2pp + 1
                    uint4 u = ((const uint4*)(sm + OF_W2F))[(ks * 16 + c * 2 + pp) * 32 + lane];
                    MMA_F16(acc[0][2 * pp],     ha[0][ks], u.x, u.y);
                    MMA_F16(acc[1][2 * pp],     ha[1][ks], u.x, u.y);
                    MMA_F16(acc[0][2 * pp + 1], ha[0][ks], u.z, u.w);
                    MMA_F16(acc[1][2 * pp + 1], ha[1][ks], u.z, u.w);
                }
            // ---- packed f32x2 epilogue: pacc2 += (acc + bb) * h ----
            u64 pacc2[2][2][2];
#pragma unroll
            for (int mt = 0; mt < 2; mt++)
#pragma unroll
                for (int rr = 0; rr < 2; rr++) {
                    pacc2[mt][rr][0] = 0ULL; pacc2[mt][rr][1] = 0ULL;
                }
#pragma unroll
            for (int nt = 0; nt < 4; nt++) {
                const int ntg = c * 4 + nt;
                const u64 bbp = *(const u64*)(sm + OF_B2 + ntg * 8 + 2 * q);
                const int hs = nt & 1;   // h pair select
                const int ml = nt >> 1;  // m-sub within chunk
#pragma unroll
                for (int mt = 0; mt < 2; mt++) {
                    u64 a01 = pk2(acc[mt][nt][0], acc[mt][nt][1]);
                    u64 a23 = pk2(acc[mt][nt][2], acc[mt][nt][3]);
                    pacc2[mt][0][ml] = ffma2(fadd2(a01, bbp), hu[mt][0][hs], pacc2[mt][0][ml]);
                    pacc2[mt][1][ml] = ffma2(fadd2(a23, bbp), hu[mt][1][hs], pacc2[mt][1][ml]);
                }
            }
#pragma unroll
            for (int mt = 0; mt < 2; mt++)
#pragma unroll
                for (int rr = 0; rr < 2; rr++) {
                    float p0 = losum(pacc2[mt][rr][0]);
                    float p1 = losum(pacc2[mt][rr][1]);
                    p0 += __shfl_xor_sync(0xFFFFFFFFu, p0, 1);
                    p0 += __shfl_xor_sync(0xFFFFFFFFu, p0, 2);
                    p1 += __shfl_xor_sync(0xFFFFFFFFu, p1, 1);
                    p1 += __shfl_xor_sync(0xFFFFFFFFu, p1, 2);
                    if ((c & 1) == 0) {
                        vbuf[mt][rr][0] = p0;
                        vbuf[mt][rr][1] = p1;
                    } else if (q == 0 && vld[mt][rr]) {
                        red_add_v4(out + (size_t)node[mt][rr] * 16 + 2 * (c - 1),
                                   vbuf[mt][rr][0], vbuf[mt][rr][1], p0, p1);
                    }
                }
        }
        // no __syncthreads: E/H rows are warp-private; pipeline is per-warp
    }
}

// ---------------- launch ----------------
extern "C" void kernel_launch(void* const* d_in, const int* in_sizes, int n_in,
                              void* d_out, int out_size) {
    const int*   index_v = nullptr;
    const float* h_w = nullptr;
    const float* e_vw = nullptr;
    const float* W1 = nullptr;
    const float* b1 = nullptr;
    const float* W2 = nullptr;
    const float* b2 = nullptr;

    int big_idx[8]; long long big_sz[8]; int nb = 0;
    for (int i = 0; i < n_in; i++) {
        long long s = in_sizes[i];
        if (s == 1024)       W1 = (const float*)d_in[i];
        else if (s == 64)    b1 = (const float*)d_in[i];
        else if (s == 16384) W2 = (const float*)d_in[i];
        else if (s == 256)   b2 = (const float*)d_in[i];
        else if (s > 100000 && nb < 8) { big_idx[nb] = i; big_sz[nb] = s; nb++; }
    }
    long long min_sz = big_sz[0]; int min_pos = 0;
    for (int i = 1; i < nb; i++)
        if (big_sz[i] < min_sz) { min_sz = big_sz[i]; min_pos = i; }
    index_v = (const int*)d_in[big_idx[min_pos]];
    int n_edge = (int)min_sz;
    bool got_h = false;
    for (int i = 0; i < nb; i++) {
        if (i == min_pos) continue;
        if (!got_h) { h_w = (const float*)d_in[big_idx[i]]; got_h = true; }
        else        { e_vw = (const float*)d_in[big_idx[i]]; }
    }

    float* out = (float*)d_out;
    cudaMemsetAsync(out, 0, (size_t)out_size * sizeof(float));

    static bool attr_set = false;
    if (!attr_set) {
        cudaFuncSetAttribute(msg_mma_kernel,
                             cudaFuncAttributeMaxDynamicSharedMemorySize,
                             SMEM_FLOATS * (int)sizeof(float));
        attr_set = true;
    }
    int ntiles = (n_edge + TILE - 1) / TILE;
    int grid = ntiles < 304 ? ntiles : 304;   // 2 CTAs/SM x 152 SMs
    msg_mma_kernel<<<grid, TPB, SMEM_FLOATS * sizeof(float)>>>(
        index_v, h_w, e_vw, W1, b1, W2, b2, out, n_edge);
}